// round 14
// baseline (speedup 1.0000x reference)
#include <cuda_runtime.h>
#include <cuda_fp16.h>

#define NN 262144
#define EE 4194304
#define GG 1024

struct __align__(32) Row32 { uint4 a, b; };   // 16 halves = 32 bytes

// Scratch (static __device__ — no allocation allowed)
__device__ float  g_deg[NN];
__device__ float  g_dinv[NN];
__device__ float4 g_Xp[NN];        // (di*x0, di*x1, di*x2, di)
__device__ float4 g_aggX[NN];      // layer-1 aggregate of di*X (.w = garbage)
__device__ float4 g_h[NN * 4];     // fp32 node features h (16 floats)
__device__ Row32  g_hh[NN];        // fp16 di*h (32B per node)
__device__ Row32  g_aggh[NN];      // layer-2 fp16 aggregate (32B per node)
__device__ float4 g_pooled[GG * 4];

__device__ __forceinline__ float lrelu(float x) {
    return x >= 0.0f ? x : 0.01f * x;
}

// ---------------------------------------------------------------------------
// K0: deg = 0 (self-loop +1 folded into prep)
__global__ void k_init() {
    int i = blockIdx.x * blockDim.x + threadIdx.x;
    if (i < NN) g_deg[i] = 0.0f;
}

// K1: deg[dst] += ew  (8 edges per thread, vectorized loads)
__global__ void k_deg(const int* __restrict__ dst, const float* __restrict__ ew) {
    int t = blockIdx.x * blockDim.x + threadIdx.x;
    if (t * 8 >= EE) return;
#pragma unroll
    for (int q = 0; q < 2; q++) {
        int4   d4 = ((const int4*)dst)[2 * t + q];
        float4 w4 = ((const float4*)ew)[2 * t + q];
        atomicAdd(&g_deg[d4.x], w4.x);
        atomicAdd(&g_deg[d4.y], w4.y);
        atomicAdd(&g_deg[d4.z], w4.z);
        atomicAdd(&g_deg[d4.w], w4.w);
    }
}

// K2: dinv = rsqrt(1+deg); Xp = (di*x, di); aggX = 0
__global__ void k_prep(const float* __restrict__ X) {
    int i = blockIdx.x * blockDim.x + threadIdx.x;
    if (i >= NN) return;
    float di = rsqrtf(1.0f + g_deg[i]);
    g_dinv[i] = di;
    g_Xp[i] = make_float4(di * X[i * 3 + 0], di * X[i * 3 + 1], di * X[i * 3 + 2], di);
    g_aggX[i] = make_float4(0.f, 0.f, 0.f, 0.f);
}

// K3: layer-1 edge scatter. One thread per edge, ONE 16B random gather,
// ONE red.v4.f32.  aggX[dst] += ew * Xp[src]  (Xp pre-scaled by dinv[src])
__global__ void __launch_bounds__(256) k_edge1(const int* __restrict__ src,
                                               const int* __restrict__ dst,
                                               const float* __restrict__ ew) {
    int e = blockIdx.x * blockDim.x + threadIdx.x;
    if (e >= EE) return;
    int s = __ldg(&src[e]);
    int d = __ldg(&dst[e]);
    float w = __ldg(&ew[e]);
    float4 x = g_Xp[s];
    float4* p = &g_aggX[d];
    asm volatile("red.global.add.v4.f32 [%0], {%1, %2, %3, %4};" ::
                 "l"(p), "f"(x.x * w), "f"(x.y * w), "f"(x.z * w), "f"(x.w * w)
                 : "memory");
}

// K4: a = di*(aggX + Xp)  [= di*agg + di^2*x]; h = leaky(a@W1+b1)
//     -> g_h fp32, g_hh = fp16(di*h); g_aggh = 0
__global__ void k_mid(const float* __restrict__ W1, const float* __restrict__ b1) {
    __shared__ float sW[48];
    __shared__ float sb[16];
    if (threadIdx.x < 48) sW[threadIdx.x] = W1[threadIdx.x];
    if (threadIdx.x < 16) sb[threadIdx.x] = b1[threadIdx.x];
    __syncthreads();
    int i = blockIdx.x * blockDim.x + threadIdx.x;
    if (i >= NN) return;
    float4 xp = g_Xp[i];
    float di = xp.w;
    float4 ax = g_aggX[i];
    float a0 = di * (ax.x + xp.x);
    float a1 = di * (ax.y + xp.y);
    float a2 = di * (ax.z + xp.z);
    unsigned int hp[8];
#pragma unroll
    for (int c = 0; c < 4; c++) {
        float4 h;
        h.x = lrelu(a0 * sW[4 * c + 0] + a1 * sW[16 + 4 * c + 0] + a2 * sW[32 + 4 * c + 0] + sb[4 * c + 0]);
        h.y = lrelu(a0 * sW[4 * c + 1] + a1 * sW[16 + 4 * c + 1] + a2 * sW[32 + 4 * c + 1] + sb[4 * c + 1]);
        h.z = lrelu(a0 * sW[4 * c + 2] + a1 * sW[16 + 4 * c + 2] + a2 * sW[32 + 4 * c + 2] + sb[4 * c + 2]);
        h.w = lrelu(a0 * sW[4 * c + 3] + a1 * sW[16 + 4 * c + 3] + a2 * sW[32 + 4 * c + 3] + sb[4 * c + 3]);
        g_h[i * 4 + c] = h;
        __half2 lo = __floats2half2_rn(di * h.x, di * h.y);
        __half2 hi = __floats2half2_rn(di * h.z, di * h.w);
        hp[2 * c + 0] = *(unsigned int*)&lo;
        hp[2 * c + 1] = *(unsigned int*)&hi;
    }
    Row32 r;
    r.a = make_uint4(hp[0], hp[1], hp[2], hp[3]);
    r.b = make_uint4(hp[4], hp[5], hp[6], hp[7]);
    g_hh[i] = r;
    Row32 z;
    z.a = make_uint4(0u, 0u, 0u, 0u);
    z.b = make_uint4(0u, 0u, 0u, 0u);
    g_aggh[i] = z;
}

// K5: layer-2 edge scatter. TWO threads per edge: each gathers one 16B half
// of the fp16 row (pair shares a 128B line) and issues one
// red.global.add.noftz.v4.f16x2.  aggh[dst] += ew * hh[src]
__global__ void __launch_bounds__(256) k_edge2(const int* __restrict__ src,
                                               const int* __restrict__ dst,
                                               const float* __restrict__ ew) {
    unsigned int t = blockIdx.x * blockDim.x + threadIdx.x;
    if (t >= 2u * EE) return;
    int e = (int)(t >> 1);
    int half = (int)(t & 1u);
    int s = __ldg(&src[e]);
    int d = __ldg(&dst[e]);
    float w = __ldg(&ew[e]);
    uint4 q = ((const uint4*)&g_hh[s])[half];
    unsigned int in[4] = {q.x, q.y, q.z, q.w};
    unsigned int outp[4];
#pragma unroll
    for (int k = 0; k < 4; k++) {
        __half2 hv = *(__half2*)&in[k];
        float2 f = __half22float2(hv);
        __half2 r = __floats2half2_rn(f.x * w, f.y * w);
        outp[k] = *(unsigned int*)&r;
    }
    uint4* p = ((uint4*)&g_aggh[d]) + half;
    asm volatile("red.global.add.noftz.v4.f16x2 [%0], {%1, %2, %3, %4};" ::
                 "l"(p), "r"(outp[0]), "r"(outp[1]), "r"(outp[2]), "r"(outp[3])
                 : "memory");
}

// K6: u = di*aggh + di^2*h ; out2 = leaky(u @ W2 + b2) -> g_h
__global__ void k_post(const float* __restrict__ W2, const float* __restrict__ b2) {
    __shared__ float sW[256];
    __shared__ float sb[16];
    for (int t = threadIdx.x; t < 256; t += blockDim.x) sW[t] = W2[t];
    if (threadIdx.x < 16) sb[threadIdx.x] = b2[threadIdx.x];
    __syncthreads();
    int i = blockIdx.x * blockDim.x + threadIdx.x;
    if (i >= NN) return;
    float di = g_dinv[i];
    float di2 = di * di;
    Row32 ar = g_aggh[i];
    unsigned int ap[8] = {ar.a.x, ar.a.y, ar.a.z, ar.a.w,
                          ar.b.x, ar.b.y, ar.b.z, ar.b.w};
    float u[16];
#pragma unroll
    for (int k = 0; k < 8; k++) {
        __half2 hv = *(__half2*)&ap[k];
        float2 f = __half22float2(hv);
        u[2 * k + 0] = di * f.x;
        u[2 * k + 1] = di * f.y;
    }
#pragma unroll
    for (int c = 0; c < 4; c++) {
        float4 v = g_h[i * 4 + c];
        u[4 * c + 0] += di2 * v.x;
        u[4 * c + 1] += di2 * v.y;
        u[4 * c + 2] += di2 * v.z;
        u[4 * c + 3] += di2 * v.w;
    }
    float4 o[4];
#pragma unroll
    for (int c = 0; c < 4; c++) {
        float h0 = sb[4 * c + 0], h1 = sb[4 * c + 1], h2 = sb[4 * c + 2], h3 = sb[4 * c + 3];
#pragma unroll
        for (int k = 0; k < 16; k++) {
            float uk = u[k];
            h0 += uk * sW[k * 16 + 4 * c + 0];
            h1 += uk * sW[k * 16 + 4 * c + 1];
            h2 += uk * sW[k * 16 + 4 * c + 2];
            h3 += uk * sW[k * 16 + 4 * c + 3];
        }
        o[c] = make_float4(lrelu(h0), lrelu(h1), lrelu(h2), lrelu(h3));
    }
#pragma unroll
    for (int c = 0; c < 4; c++) g_h[i * 4 + c] = o[c];
}

// K7: mean pool per graph. One block (128 threads) per graph; binary search bounds.
__global__ void k_pool(const int* __restrict__ B) {
    int g = blockIdx.x;
    int lo = 0, hi = NN;
    while (lo < hi) { int m = (lo + hi) >> 1; if (__ldg(&B[m]) < g) lo = m + 1; else hi = m; }
    int start = lo;
    lo = start; hi = NN;
    while (lo < hi) { int m = (lo + hi) >> 1; if (__ldg(&B[m]) < g + 1) lo = m + 1; else hi = m; }
    int end = lo;
    int cnt = end - start;

    int c = threadIdx.x & 3;
    int k = threadIdx.x >> 2;  // 0..31
    float4 acc = make_float4(0.f, 0.f, 0.f, 0.f);
    for (int n = start + k; n < end; n += 32) {
        float4 v = g_h[n * 4 + c];
        acc.x += v.x; acc.y += v.y; acc.z += v.z; acc.w += v.w;
    }
    __shared__ float4 sm[128];
    sm[threadIdx.x] = acc;
    __syncthreads();
#pragma unroll
    for (int off = 64; off >= 4; off >>= 1) {
        if (threadIdx.x < off) {
            float4 o = sm[threadIdx.x + off];
            float4 m = sm[threadIdx.x];
            sm[threadIdx.x] = make_float4(m.x + o.x, m.y + o.y, m.z + o.z, m.w + o.w);
        }
        __syncthreads();
    }
    if (threadIdx.x < 4) {
        float inv = 1.0f / fmaxf((float)cnt, 1.0f);
        float4 s = sm[threadIdx.x];
        g_pooled[g * 4 + threadIdx.x] = make_float4(s.x * inv, s.y * inv, s.z * inv, s.w * inv);
    }
}

// K8: MLP heads. One thread per graph.
__global__ void k_mlp(const float* __restrict__ Wp1, const float* __restrict__ bp1,
                      const float* __restrict__ Wp2, const float* __restrict__ bp2,
                      const float* __restrict__ Wp3, const float* __restrict__ bp3,
                      const float* __restrict__ Wt1, const float* __restrict__ bt1,
                      const float* __restrict__ Wt2, const float* __restrict__ bt2,
                      const float* __restrict__ Wt3, const float* __restrict__ bt3,
                      float* __restrict__ out) {
    __shared__ float sWp1[256], sWp2[256], sWp3[32], sWt1[256], sWt2[256], sWt3[32];
    __shared__ float sbp1[16], sbp2[16], sbp3[2], sbt1[16], sbt2[16], sbt3[2];
    for (int t = threadIdx.x; t < 256; t += blockDim.x) {
        sWp1[t] = Wp1[t]; sWp2[t] = Wp2[t]; sWt1[t] = Wt1[t]; sWt2[t] = Wt2[t];
    }
    if (threadIdx.x < 32) { sWp3[threadIdx.x] = Wp3[threadIdx.x]; sWt3[threadIdx.x] = Wt3[threadIdx.x]; }
    if (threadIdx.x < 16) {
        sbp1[threadIdx.x] = bp1[threadIdx.x]; sbp2[threadIdx.x] = bp2[threadIdx.x];
        sbt1[threadIdx.x] = bt1[threadIdx.x]; sbt2[threadIdx.x] = bt2[threadIdx.x];
    }
    if (threadIdx.x < 2) { sbp3[threadIdx.x] = bp3[threadIdx.x]; sbt3[threadIdx.x] = bt3[threadIdx.x]; }
    __syncthreads();

    int g = blockIdx.x * blockDim.x + threadIdx.x;
    if (g >= GG) return;
    float p[16];
#pragma unroll
    for (int c = 0; c < 4; c++) {
        float4 v = g_pooled[g * 4 + c];
        p[4 * c + 0] = v.x; p[4 * c + 1] = v.y; p[4 * c + 2] = v.z; p[4 * c + 3] = v.w;
    }
    float a[16], b[16];
#pragma unroll
    for (int j = 0; j < 16; j++) {
        float s = sbp1[j];
#pragma unroll
        for (int k = 0; k < 16; k++) s += p[k] * sWp1[k * 16 + j];
        a[j] = lrelu(s);
    }
#pragma unroll
    for (int j = 0; j < 16; j++) {
        float s = sbp2[j];
#pragma unroll
        for (int k = 0; k < 16; k++) s += a[k] * sWp2[k * 16 + j];
        b[j] = lrelu(s);
    }
    float phi0 = sbp3[0], phi1 = sbp3[1];
#pragma unroll
    for (int k = 0; k < 16; k++) { phi0 += b[k] * sWp3[k * 2 + 0]; phi1 += b[k] * sWp3[k * 2 + 1]; }
#pragma unroll
    for (int j = 0; j < 16; j++) {
        float s = sbt1[j];
#pragma unroll
        for (int k = 0; k < 16; k++) s += p[k] * sWt1[k * 16 + j];
        a[j] = lrelu(s);
    }
#pragma unroll
    for (int j = 0; j < 16; j++) {
        float s = sbt2[j];
#pragma unroll
        for (int k = 0; k < 16; k++) s += a[k] * sWt2[k * 16 + j];
        b[j] = lrelu(s);
    }
    float th0 = sbt3[0], th1 = sbt3[1];
#pragma unroll
    for (int k = 0; k < 16; k++) { th0 += b[k] * sWt3[k * 2 + 0]; th1 += b[k] * sWt3[k * 2 + 1]; }

    out[g * 4 + 0] = phi0;
    out[g * 4 + 1] = phi1;
    out[g * 4 + 2] = th0;
    out[g * 4 + 3] = th1;
}

// ---------------------------------------------------------------------------
extern "C" void kernel_launch(void* const* d_in, const int* in_sizes, int n_in,
                              void* d_out, int out_size) {
    const float* X   = (const float*)d_in[0];
    const int*   ei  = (const int*)d_in[1];
    const float* ew  = (const float*)d_in[2];
    const int*   Bt  = (const int*)d_in[3];
    int base = 4;
    if (base < n_in && in_sizes[base] == 1) base++;  // skip scalar num_graphs
    const float* W1  = (const float*)d_in[base + 0];
    const float* b1  = (const float*)d_in[base + 1];
    const float* W2  = (const float*)d_in[base + 2];
    const float* b2  = (const float*)d_in[base + 3];
    const float* Wp1 = (const float*)d_in[base + 4];
    const float* bp1 = (const float*)d_in[base + 5];
    const float* Wp2 = (const float*)d_in[base + 6];
    const float* bp2 = (const float*)d_in[base + 7];
    const float* Wp3 = (const float*)d_in[base + 8];
    const float* bp3 = (const float*)d_in[base + 9];
    const float* Wt1 = (const float*)d_in[base + 10];
    const float* bt1 = (const float*)d_in[base + 11];
    const float* Wt2 = (const float*)d_in[base + 12];
    const float* bt2 = (const float*)d_in[base + 13];
    const float* Wt3 = (const float*)d_in[base + 14];
    const float* bt3 = (const float*)d_in[base + 15];

    const int* src = ei;
    const int* dst = ei + EE;
    float* out = (float*)d_out;

    k_init<<<NN / 256, 256>>>();
    k_deg<<<EE / 8 / 256, 256>>>(dst, ew);
    k_prep<<<NN / 256, 256>>>(X);
    k_edge1<<<EE / 256, 256>>>(src, dst, ew);
    k_mid<<<NN / 256, 256>>>(W1, b1);
    k_edge2<<<(2u * EE) / 256, 256>>>(src, dst, ew);
    k_post<<<NN / 256, 256>>>(W2, b2);
    k_pool<<<GG, 128>>>(Bt);
    k_mlp<<<(GG + 255) / 256, 256>>>(Wp1, bp1, Wp2, bp2, Wp3, bp3,
                                     Wt1, bt1, Wt2, bt2, Wt3, bt3, out);
}

// round 15
// speedup vs baseline: 1.5142x; 1.5142x over previous
#include <cuda_runtime.h>
#include <cuda_fp16.h>

#define NN 262144
#define EE 4194304
#define GG 1024

struct __align__(32) Row32 { uint4 a, b; };   // 16 halves = 32 bytes

// Scratch (static __device__ — no allocation allowed)
__device__ float  g_deg[NN];
__device__ float  g_dinv[NN];
__device__ float4 g_Xp[NN];        // (di*x0, di*x1, di*x2, di)
__device__ float4 g_aggX[NN];      // layer-1 aggregate of di*X (.w = garbage)
__device__ float4 g_h[NN * 4];     // fp32 node features h (16 floats)
__device__ Row32  g_hh[NN];        // fp16 di*h (32B per node)
__device__ Row32  g_aggh[NN];      // layer-2 fp16 aggregate (32B per node)
__device__ float4 g_pooled[GG * 4];

__device__ __forceinline__ float lrelu(float x) {
    return x >= 0.0f ? x : 0.01f * x;
}

// ---------------------------------------------------------------------------
// K0: deg = 0 (self-loop +1 folded into prep)
__global__ void k_init() {
    int i = blockIdx.x * blockDim.x + threadIdx.x;
    if (i < NN) g_deg[i] = 0.0f;
}

// K1: deg[dst] += ew  (4 edges per thread, vectorized loads)
__global__ void k_deg(const int* __restrict__ dst, const float* __restrict__ ew) {
    int t = blockIdx.x * blockDim.x + threadIdx.x;
    if (t * 4 >= EE) return;
    int4   d4 = ((const int4*)dst)[t];
    float4 w4 = ((const float4*)ew)[t];
    atomicAdd(&g_deg[d4.x], w4.x);
    atomicAdd(&g_deg[d4.y], w4.y);
    atomicAdd(&g_deg[d4.z], w4.z);
    atomicAdd(&g_deg[d4.w], w4.w);
}

// K2: dinv = rsqrt(1+deg); Xp = (di*x, di); aggX = 0
__global__ void k_prep(const float* __restrict__ X) {
    int i = blockIdx.x * blockDim.x + threadIdx.x;
    if (i >= NN) return;
    float di = rsqrtf(1.0f + g_deg[i]);
    g_dinv[i] = di;
    g_Xp[i] = make_float4(di * X[i * 3 + 0], di * X[i * 3 + 1], di * X[i * 3 + 2], di);
    g_aggX[i] = make_float4(0.f, 0.f, 0.f, 0.f);
}

// K3: layer-1 edge scatter. One thread per edge, ONE 16B random gather,
// ONE red.v4.f32.  aggX[dst] += ew * Xp[src]  (Xp pre-scaled by dinv[src])
__global__ void __launch_bounds__(256) k_edge1(const int* __restrict__ src,
                                               const int* __restrict__ dst,
                                               const float* __restrict__ ew) {
    int e = blockIdx.x * blockDim.x + threadIdx.x;
    if (e >= EE) return;
    int s = __ldg(&src[e]);
    int d = __ldg(&dst[e]);
    float w = __ldg(&ew[e]);
    float4 x = g_Xp[s];
    float4* p = &g_aggX[d];
    asm volatile("red.global.add.v4.f32 [%0], {%1, %2, %3, %4};" ::
                 "l"(p), "f"(x.x * w), "f"(x.y * w), "f"(x.z * w), "f"(x.w * w)
                 : "memory");
}

// K4: a = di*(aggX + Xp)  [= di*agg + di^2*x]; h = leaky(a@W1+b1)
//     -> g_h fp32, g_hh = fp16(di*h); g_aggh = 0
__global__ void k_mid(const float* __restrict__ W1, const float* __restrict__ b1) {
    __shared__ float sW[48];
    __shared__ float sb[16];
    if (threadIdx.x < 48) sW[threadIdx.x] = W1[threadIdx.x];
    if (threadIdx.x < 16) sb[threadIdx.x] = b1[threadIdx.x];
    __syncthreads();
    int i = blockIdx.x * blockDim.x + threadIdx.x;
    if (i >= NN) return;
    float4 xp = g_Xp[i];
    float di = xp.w;
    float4 ax = g_aggX[i];
    float a0 = di * (ax.x + xp.x);
    float a1 = di * (ax.y + xp.y);
    float a2 = di * (ax.z + xp.z);
    unsigned int hp[8];
#pragma unroll
    for (int c = 0; c < 4; c++) {
        float4 h;
        h.x = lrelu(a0 * sW[4 * c + 0] + a1 * sW[16 + 4 * c + 0] + a2 * sW[32 + 4 * c + 0] + sb[4 * c + 0]);
        h.y = lrelu(a0 * sW[4 * c + 1] + a1 * sW[16 + 4 * c + 1] + a2 * sW[32 + 4 * c + 1] + sb[4 * c + 1]);
        h.z = lrelu(a0 * sW[4 * c + 2] + a1 * sW[16 + 4 * c + 2] + a2 * sW[32 + 4 * c + 2] + sb[4 * c + 2]);
        h.w = lrelu(a0 * sW[4 * c + 3] + a1 * sW[16 + 4 * c + 3] + a2 * sW[32 + 4 * c + 3] + sb[4 * c + 3]);
        g_h[i * 4 + c] = h;
        __half2 lo = __floats2half2_rn(di * h.x, di * h.y);
        __half2 hi = __floats2half2_rn(di * h.z, di * h.w);
        hp[2 * c + 0] = *(unsigned int*)&lo;
        hp[2 * c + 1] = *(unsigned int*)&hi;
    }
    Row32 r;
    r.a = make_uint4(hp[0], hp[1], hp[2], hp[3]);
    r.b = make_uint4(hp[4], hp[5], hp[6], hp[7]);
    g_hh[i] = r;
    Row32 z;
    z.a = make_uint4(0u, 0u, 0u, 0u);
    z.b = make_uint4(0u, 0u, 0u, 0u);
    g_aggh[i] = z;
}

// K5: layer-2 edge scatter. TWO threads per edge: each gathers one 16B half
// of the fp16 row (pair shares a 128B line) and issues one
// red.global.add.noftz.v4.f16x2.  aggh[dst] += ew * hh[src]
__global__ void __launch_bounds__(256) k_edge2(const int* __restrict__ src,
                                               const int* __restrict__ dst,
                                               const float* __restrict__ ew) {
    unsigned int t = blockIdx.x * blockDim.x + threadIdx.x;
    if (t >= 2u * EE) return;
    int e = (int)(t >> 1);
    int half = (int)(t & 1u);
    int s = __ldg(&src[e]);
    int d = __ldg(&dst[e]);
    float w = __ldg(&ew[e]);
    uint4 q = ((const uint4*)&g_hh[s])[half];
    unsigned int in[4] = {q.x, q.y, q.z, q.w};
    unsigned int outp[4];
#pragma unroll
    for (int k = 0; k < 4; k++) {
        __half2 hv = *(__half2*)&in[k];
        float2 f = __half22float2(hv);
        __half2 r = __floats2half2_rn(f.x * w, f.y * w);
        outp[k] = *(unsigned int*)&r;
    }
    uint4* p = ((uint4*)&g_aggh[d]) + half;
    asm volatile("red.global.add.noftz.v4.f16x2 [%0], {%1, %2, %3, %4};" ::
                 "l"(p), "r"(outp[0]), "r"(outp[1]), "r"(outp[2]), "r"(outp[3])
                 : "memory");
}

// K6: u = di*aggh + di^2*h ; out2 = leaky(u @ W2 + b2) -> g_h
__global__ void k_post(const float* __restrict__ W2, const float* __restrict__ b2) {
    __shared__ float sW[256];
    __shared__ float sb[16];
    for (int t = threadIdx.x; t < 256; t += blockDim.x) sW[t] = W2[t];
    if (threadIdx.x < 16) sb[threadIdx.x] = b2[threadIdx.x];
    __syncthreads();
    int i = blockIdx.x * blockDim.x + threadIdx.x;
    if (i >= NN) return;
    float di = g_dinv[i];
    float di2 = di * di;
    Row32 ar = g_aggh[i];
    unsigned int ap[8] = {ar.a.x, ar.a.y, ar.a.z, ar.a.w,
                          ar.b.x, ar.b.y, ar.b.z, ar.b.w};
    float u[16];
#pragma unroll
    for (int k = 0; k < 8; k++) {
        __half2 hv = *(__half2*)&ap[k];
        float2 f = __half22float2(hv);
        u[2 * k + 0] = di * f.x;
        u[2 * k + 1] = di * f.y;
    }
#pragma unroll
    for (int c = 0; c < 4; c++) {
        float4 v = g_h[i * 4 + c];
        u[4 * c + 0] += di2 * v.x;
        u[4 * c + 1] += di2 * v.y;
        u[4 * c + 2] += di2 * v.z;
        u[4 * c + 3] += di2 * v.w;
    }
    float4 o[4];
#pragma unroll
    for (int c = 0; c < 4; c++) {
        float h0 = sb[4 * c + 0], h1 = sb[4 * c + 1], h2 = sb[4 * c + 2], h3 = sb[4 * c + 3];
#pragma unroll
        for (int k = 0; k < 16; k++) {
            float uk = u[k];
            h0 += uk * sW[k * 16 + 4 * c + 0];
            h1 += uk * sW[k * 16 + 4 * c + 1];
            h2 += uk * sW[k * 16 + 4 * c + 2];
            h3 += uk * sW[k * 16 + 4 * c + 3];
        }
        o[c] = make_float4(lrelu(h0), lrelu(h1), lrelu(h2), lrelu(h3));
    }
#pragma unroll
    for (int c = 0; c < 4; c++) g_h[i * 4 + c] = o[c];
}

// K7: mean pool per graph. One block (128 threads) per graph; binary search bounds.
__global__ void k_pool(const int* __restrict__ B) {
    int g = blockIdx.x;
    int lo = 0, hi = NN;
    while (lo < hi) { int m = (lo + hi) >> 1; if (__ldg(&B[m]) < g) lo = m + 1; else hi = m; }
    int start = lo;
    lo = start; hi = NN;
    while (lo < hi) { int m = (lo + hi) >> 1; if (__ldg(&B[m]) < g + 1) lo = m + 1; else hi = m; }
    int end = lo;
    int cnt = end - start;

    int c = threadIdx.x & 3;
    int k = threadIdx.x >> 2;  // 0..31
    float4 acc = make_float4(0.f, 0.f, 0.f, 0.f);
    for (int n = start + k; n < end; n += 32) {
        float4 v = g_h[n * 4 + c];
        acc.x += v.x; acc.y += v.y; acc.z += v.z; acc.w += v.w;
    }
    __shared__ float4 sm[128];
    sm[threadIdx.x] = acc;
    __syncthreads();
#pragma unroll
    for (int off = 64; off >= 4; off >>= 1) {
        if (threadIdx.x < off) {
            float4 o = sm[threadIdx.x + off];
            float4 m = sm[threadIdx.x];
            sm[threadIdx.x] = make_float4(m.x + o.x, m.y + o.y, m.z + o.z, m.w + o.w);
        }
        __syncthreads();
    }
    if (threadIdx.x < 4) {
        float inv = 1.0f / fmaxf((float)cnt, 1.0f);
        float4 s = sm[threadIdx.x];
        g_pooled[g * 4 + threadIdx.x] = make_float4(s.x * inv, s.y * inv, s.z * inv, s.w * inv);
    }
}

// K8: MLP heads. One thread per graph.
__global__ void k_mlp(const float* __restrict__ Wp1, const float* __restrict__ bp1,
                      const float* __restrict__ Wp2, const float* __restrict__ bp2,
                      const float* __restrict__ Wp3, const float* __restrict__ bp3,
                      const float* __restrict__ Wt1, const float* __restrict__ bt1,
                      const float* __restrict__ Wt2, const float* __restrict__ bt2,
                      const float* __restrict__ Wt3, const float* __restrict__ bt3,
                      float* __restrict__ out) {
    __shared__ float sWp1[256], sWp2[256], sWp3[32], sWt1[256], sWt2[256], sWt3[32];
    __shared__ float sbp1[16], sbp2[16], sbp3[2], sbt1[16], sbt2[16], sbt3[2];
    for (int t = threadIdx.x; t < 256; t += blockDim.x) {
        sWp1[t] = Wp1[t]; sWp2[t] = Wp2[t]; sWt1[t] = Wt1[t]; sWt2[t] = Wt2[t];
    }
    if (threadIdx.x < 32) { sWp3[threadIdx.x] = Wp3[threadIdx.x]; sWt3[threadIdx.x] = Wt3[threadIdx.x]; }
    if (threadIdx.x < 16) {
        sbp1[threadIdx.x] = bp1[threadIdx.x]; sbp2[threadIdx.x] = bp2[threadIdx.x];
        sbt1[threadIdx.x] = bt1[threadIdx.x]; sbt2[threadIdx.x] = bt2[threadIdx.x];
    }
    if (threadIdx.x < 2) { sbp3[threadIdx.x] = bp3[threadIdx.x]; sbt3[threadIdx.x] = bt3[threadIdx.x]; }
    __syncthreads();

    int g = blockIdx.x * blockDim.x + threadIdx.x;
    if (g >= GG) return;
    float p[16];
#pragma unroll
    for (int c = 0; c < 4; c++) {
        float4 v = g_pooled[g * 4 + c];
        p[4 * c + 0] = v.x; p[4 * c + 1] = v.y; p[4 * c + 2] = v.z; p[4 * c + 3] = v.w;
    }
    float a[16], b[16];
#pragma unroll
    for (int j = 0; j < 16; j++) {
        float s = sbp1[j];
#pragma unroll
        for (int k = 0; k < 16; k++) s += p[k] * sWp1[k * 16 + j];
        a[j] = lrelu(s);
    }
#pragma unroll
    for (int j = 0; j < 16; j++) {
        float s = sbp2[j];
#pragma unroll
        for (int k = 0; k < 16; k++) s += a[k] * sWp2[k * 16 + j];
        b[j] = lrelu(s);
    }
    float phi0 = sbp3[0], phi1 = sbp3[1];
#pragma unroll
    for (int k = 0; k < 16; k++) { phi0 += b[k] * sWp3[k * 2 + 0]; phi1 += b[k] * sWp3[k * 2 + 1]; }
#pragma unroll
    for (int j = 0; j < 16; j++) {
        float s = sbt1[j];
#pragma unroll
        for (int k = 0; k < 16; k++) s += p[k] * sWt1[k * 16 + j];
        a[j] = lrelu(s);
    }
#pragma unroll
    for (int j = 0; j < 16; j++) {
        float s = sbt2[j];
#pragma unroll
        for (int k = 0; k < 16; k++) s += a[k] * sWt2[k * 16 + j];
        b[j] = lrelu(s);
    }
    float th0 = sbt3[0], th1 = sbt3[1];
#pragma unroll
    for (int k = 0; k < 16; k++) { th0 += b[k] * sWt3[k * 2 + 0]; th1 += b[k] * sWt3[k * 2 + 1]; }

    out[g * 4 + 0] = phi0;
    out[g * 4 + 1] = phi1;
    out[g * 4 + 2] = th0;
    out[g * 4 + 3] = th1;
}

// ---------------------------------------------------------------------------
extern "C" void kernel_launch(void* const* d_in, const int* in_sizes, int n_in,
                              void* d_out, int out_size) {
    const float* X   = (const float*)d_in[0];
    const int*   ei  = (const int*)d_in[1];
    const float* ew  = (const float*)d_in[2];
    const int*   Bt  = (const int*)d_in[3];
    int base = 4;
    if (base < n_in && in_sizes[base] == 1) base++;  // skip scalar num_graphs
    const float* W1  = (const float*)d_in[base + 0];
    const float* b1  = (const float*)d_in[base + 1];
    const float* W2  = (const float*)d_in[base + 2];
    const float* b2  = (const float*)d_in[base + 3];
    const float* Wp1 = (const float*)d_in[base + 4];
    const float* bp1 = (const float*)d_in[base + 5];
    const float* Wp2 = (const float*)d_in[base + 6];
    const float* bp2 = (const float*)d_in[base + 7];
    const float* Wp3 = (const float*)d_in[base + 8];
    const float* bp3 = (const float*)d_in[base + 9];
    const float* Wt1 = (const float*)d_in[base + 10];
    const float* bt1 = (const float*)d_in[base + 11];
    const float* Wt2 = (const float*)d_in[base + 12];
    const float* bt2 = (const float*)d_in[base + 13];
    const float* Wt3 = (const float*)d_in[base + 14];
    const float* bt3 = (const float*)d_in[base + 15];

    const int* src = ei;
    const int* dst = ei + EE;
    float* out = (float*)d_out;

    k_init<<<NN / 256, 256>>>();
    k_deg<<<EE / 4 / 256, 256>>>(dst, ew);
    k_prep<<<NN / 256, 256>>>(X);
    k_edge1<<<EE / 256, 256>>>(src, dst, ew);
    k_mid<<<NN / 256, 256>>>(W1, b1);
    k_edge2<<<(2u * EE) / 256, 256>>>(src, dst, ew);
    k_post<<<NN / 256, 256>>>(W2, b2);
    k_pool<<<GG, 128>>>(Bt);
    k_mlp<<<(GG + 255) / 256, 256>>>(Wp1, bp1, Wp2, bp2, Wp3, bp3,
                                     Wt1, bt1, Wt2, bt2, Wt3, bt3, out);
}

// round 16
// speedup vs baseline: 1.5598x; 1.0301x over previous
#include <cuda_runtime.h>
#include <cuda_fp16.h>

#define NN 262144
#define EE 4194304
#define GG 1024

struct __align__(32) Row32 { uint4 a, b; };   // 16 halves = 32 bytes

// Scratch (static __device__ — no allocation allowed)
__device__ float  g_deg[NN];
__device__ float4 g_Xp[NN];        // (di*x0, di*x1, di*x2, di)
__device__ float4 g_aggX[NN];      // layer-1 aggregate of di*X (.w = garbage)
__device__ float4 g_h[NN * 4];     // fp32 layer-2 output (written by k_post)
__device__ Row32  g_hh[NN];        // fp16 di*h1 (32B per node)
__device__ Row32  g_aggh[NN];      // layer-2 fp16 aggregate (32B per node)
__device__ float4 g_pooled[GG * 4];

__device__ __forceinline__ float lrelu(float x) {
    return x >= 0.0f ? x : 0.01f * x;
}

// ---------------------------------------------------------------------------
// K0: deg = 0 (self-loop +1 folded into prep)
__global__ void k_init() {
    int i = blockIdx.x * blockDim.x + threadIdx.x;
    if (i < NN) g_deg[i] = 0.0f;
}

// K1: deg[dst] += ew  (4 edges per thread, vectorized loads)
__global__ void k_deg(const int* __restrict__ dst, const float* __restrict__ ew) {
    int t = blockIdx.x * blockDim.x + threadIdx.x;
    if (t * 4 >= EE) return;
    int4   d4 = ((const int4*)dst)[t];
    float4 w4 = ((const float4*)ew)[t];
    atomicAdd(&g_deg[d4.x], w4.x);
    atomicAdd(&g_deg[d4.y], w4.y);
    atomicAdd(&g_deg[d4.z], w4.z);
    atomicAdd(&g_deg[d4.w], w4.w);
}

// K2: di = rsqrt(1+deg); Xp = (di*x, di); aggX = 0
__global__ void k_prep(const float* __restrict__ X) {
    int i = blockIdx.x * blockDim.x + threadIdx.x;
    if (i >= NN) return;
    float di = rsqrtf(1.0f + g_deg[i]);
    g_Xp[i] = make_float4(di * X[i * 3 + 0], di * X[i * 3 + 1], di * X[i * 3 + 2], di);
    g_aggX[i] = make_float4(0.f, 0.f, 0.f, 0.f);
}

// K3: layer-1 edge scatter. One thread per edge, ONE 16B random gather,
// ONE red.v4.f32.  aggX[dst] += ew * Xp[src]  (Xp pre-scaled by dinv[src])
__global__ void __launch_bounds__(256) k_edge1(const int* __restrict__ src,
                                               const int* __restrict__ dst,
                                               const float* __restrict__ ew) {
    int e = blockIdx.x * blockDim.x + threadIdx.x;
    if (e >= EE) return;
    int s = __ldg(&src[e]);
    int d = __ldg(&dst[e]);
    float w = __ldg(&ew[e]);
    float4 x = g_Xp[s];
    float4* p = &g_aggX[d];
    asm volatile("red.global.add.v4.f32 [%0], {%1, %2, %3, %4};" ::
                 "l"(p), "f"(x.x * w), "f"(x.y * w), "f"(x.z * w), "f"(x.w * w)
                 : "memory");
}

// K4: a = di*(aggX + Xp); h1 = leaky(a@W1+b1); g_hh = fp16(di*h1); g_aggh = 0
//     (h1 fp32 NOT stored — recomputed in k_post)
__global__ void k_mid(const float* __restrict__ W1, const float* __restrict__ b1) {
    __shared__ float sW[48];
    __shared__ float sb[16];
    if (threadIdx.x < 48) sW[threadIdx.x] = W1[threadIdx.x];
    if (threadIdx.x < 16) sb[threadIdx.x] = b1[threadIdx.x];
    __syncthreads();
    int i = blockIdx.x * blockDim.x + threadIdx.x;
    if (i >= NN) return;
    float4 xp = g_Xp[i];
    float di = xp.w;
    float4 ax = g_aggX[i];
    float a0 = di * (ax.x + xp.x);
    float a1 = di * (ax.y + xp.y);
    float a2 = di * (ax.z + xp.z);
    unsigned int hp[8];
#pragma unroll
    for (int c = 0; c < 4; c++) {
        float h0 = lrelu(a0 * sW[4 * c + 0] + a1 * sW[16 + 4 * c + 0] + a2 * sW[32 + 4 * c + 0] + sb[4 * c + 0]);
        float h1 = lrelu(a0 * sW[4 * c + 1] + a1 * sW[16 + 4 * c + 1] + a2 * sW[32 + 4 * c + 1] + sb[4 * c + 1]);
        float h2 = lrelu(a0 * sW[4 * c + 2] + a1 * sW[16 + 4 * c + 2] + a2 * sW[32 + 4 * c + 2] + sb[4 * c + 2]);
        float h3 = lrelu(a0 * sW[4 * c + 3] + a1 * sW[16 + 4 * c + 3] + a2 * sW[32 + 4 * c + 3] + sb[4 * c + 3]);
        __half2 lo = __floats2half2_rn(di * h0, di * h1);
        __half2 hi = __floats2half2_rn(di * h2, di * h3);
        hp[2 * c + 0] = *(unsigned int*)&lo;
        hp[2 * c + 1] = *(unsigned int*)&hi;
    }
    Row32 r;
    r.a = make_uint4(hp[0], hp[1], hp[2], hp[3]);
    r.b = make_uint4(hp[4], hp[5], hp[6], hp[7]);
    g_hh[i] = r;
    Row32 z;
    z.a = make_uint4(0u, 0u, 0u, 0u);
    z.b = make_uint4(0u, 0u, 0u, 0u);
    g_aggh[i] = z;
}

// K5: layer-2 edge scatter. TWO threads per edge: each gathers one 16B half
// of the fp16 row (pair shares a 128B line) and issues one
// red.global.add.noftz.v4.f16x2.  aggh[dst] += ew * hh[src]
__global__ void __launch_bounds__(256) k_edge2(const int* __restrict__ src,
                                               const int* __restrict__ dst,
                                               const float* __restrict__ ew) {
    unsigned int t = blockIdx.x * blockDim.x + threadIdx.x;
    if (t >= 2u * EE) return;
    int e = (int)(t >> 1);
    int half = (int)(t & 1u);
    int s = __ldg(&src[e]);
    int d = __ldg(&dst[e]);
    float w = __ldg(&ew[e]);
    uint4 q = ((const uint4*)&g_hh[s])[half];
    unsigned int in[4] = {q.x, q.y, q.z, q.w};
    unsigned int outp[4];
#pragma unroll
    for (int k = 0; k < 4; k++) {
        __half2 hv = *(__half2*)&in[k];
        float2 f = __half22float2(hv);
        __half2 r = __floats2half2_rn(f.x * w, f.y * w);
        outp[k] = *(unsigned int*)&r;
    }
    uint4* p = ((uint4*)&g_aggh[d]) + half;
    asm volatile("red.global.add.noftz.v4.f16x2 [%0], {%1, %2, %3, %4};" ::
                 "l"(p), "r"(outp[0]), "r"(outp[1]), "r"(outp[2]), "r"(outp[3])
                 : "memory");
}

// K6: recompute h1 from aggX/Xp; u = di*aggh + di^2*h1;
//     out2 = leaky(u @ W2 + b2) -> g_h
__global__ void __launch_bounds__(256) k_post(const float* __restrict__ W1,
                                              const float* __restrict__ b1,
                                              const float* __restrict__ W2,
                                              const float* __restrict__ b2) {
    __shared__ float sW1[48], sb1[16];
    __shared__ float sW2[256], sb2[16];
    if (threadIdx.x < 48) sW1[threadIdx.x] = W1[threadIdx.x];
    if (threadIdx.x >= 64 && threadIdx.x < 80) sb1[threadIdx.x - 64] = b1[threadIdx.x - 64];
    for (int t = threadIdx.x; t < 256; t += blockDim.x) sW2[t] = W2[t];
    if (threadIdx.x >= 96 && threadIdx.x < 112) sb2[threadIdx.x - 96] = b2[threadIdx.x - 96];
    __syncthreads();
    int i = blockIdx.x * blockDim.x + threadIdx.x;
    if (i >= NN) return;
    float4 xp = g_Xp[i];
    float di = xp.w;
    float di2 = di * di;
    float4 ax = g_aggX[i];
    float a0 = di * (ax.x + xp.x);
    float a1 = di * (ax.y + xp.y);
    float a2 = di * (ax.z + xp.z);
    float u[16];
#pragma unroll
    for (int c = 0; c < 16; c++)
        u[c] = di2 * lrelu(a0 * sW1[c] + a1 * sW1[16 + c] + a2 * sW1[32 + c] + sb1[c]);
    Row32 ar = g_aggh[i];
    unsigned int ap[8] = {ar.a.x, ar.a.y, ar.a.z, ar.a.w,
                          ar.b.x, ar.b.y, ar.b.z, ar.b.w};
#pragma unroll
    for (int k = 0; k < 8; k++) {
        float2 f = __half22float2(*(__half2*)&ap[k]);
        u[2 * k + 0] += di * f.x;
        u[2 * k + 1] += di * f.y;
    }
#pragma unroll
    for (int c = 0; c < 4; c++) {
        float h0 = sb2[4 * c + 0], h1 = sb2[4 * c + 1], h2 = sb2[4 * c + 2], h3 = sb2[4 * c + 3];
#pragma unroll
        for (int k = 0; k < 16; k++) {
            float uk = u[k];
            h0 += uk * sW2[k * 16 + 4 * c + 0];
            h1 += uk * sW2[k * 16 + 4 * c + 1];
            h2 += uk * sW2[k * 16 + 4 * c + 2];
            h3 += uk * sW2[k * 16 + 4 * c + 3];
        }
        g_h[i * 4 + c] = make_float4(lrelu(h0), lrelu(h1), lrelu(h2), lrelu(h3));
    }
}

// K7: mean pool per graph. One block (128 threads) per graph; binary search bounds.
__global__ void k_pool(const int* __restrict__ B) {
    int g = blockIdx.x;
    int lo = 0, hi = NN;
    while (lo < hi) { int m = (lo + hi) >> 1; if (__ldg(&B[m]) < g) lo = m + 1; else hi = m; }
    int start = lo;
    lo = start; hi = NN;
    while (lo < hi) { int m = (lo + hi) >> 1; if (__ldg(&B[m]) < g + 1) lo = m + 1; else hi = m; }
    int end = lo;
    int cnt = end - start;

    int c = threadIdx.x & 3;
    int k = threadIdx.x >> 2;  // 0..31
    float4 acc = make_float4(0.f, 0.f, 0.f, 0.f);
    for (int n = start + k; n < end; n += 32) {
        float4 v = g_h[n * 4 + c];
        acc.x += v.x; acc.y += v.y; acc.z += v.z; acc.w += v.w;
    }
    __shared__ float4 sm[128];
    sm[threadIdx.x] = acc;
    __syncthreads();
#pragma unroll
    for (int off = 64; off >= 4; off >>= 1) {
        if (threadIdx.x < off) {
            float4 o = sm[threadIdx.x + off];
            float4 m = sm[threadIdx.x];
            sm[threadIdx.x] = make_float4(m.x + o.x, m.y + o.y, m.z + o.z, m.w + o.w);
        }
        __syncthreads();
    }
    if (threadIdx.x < 4) {
        float inv = 1.0f / fmaxf((float)cnt, 1.0f);
        float4 s = sm[threadIdx.x];
        g_pooled[g * 4 + threadIdx.x] = make_float4(s.x * inv, s.y * inv, s.z * inv, s.w * inv);
    }
}

// K8: MLP heads. One thread per graph.
__global__ void k_mlp(const float* __restrict__ Wp1, const float* __restrict__ bp1,
                      const float* __restrict__ Wp2, const float* __restrict__ bp2,
                      const float* __restrict__ Wp3, const float* __restrict__ bp3,
                      const float* __restrict__ Wt1, const float* __restrict__ bt1,
                      const float* __restrict__ Wt2, const float* __restrict__ bt2,
                      const float* __restrict__ Wt3, const float* __restrict__ bt3,
                      float* __restrict__ out) {
    __shared__ float sWp1[256], sWp2[256], sWp3[32], sWt1[256], sWt2[256], sWt3[32];
    __shared__ float sbp1[16], sbp2[16], sbp3[2], sbt1[16], sbt2[16], sbt3[2];
    for (int t = threadIdx.x; t < 256; t += blockDim.x) {
        sWp1[t] = Wp1[t]; sWp2[t] = Wp2[t]; sWt1[t] = Wt1[t]; sWt2[t] = Wt2[t];
    }
    if (threadIdx.x < 32) { sWp3[threadIdx.x] = Wp3[threadIdx.x]; sWt3[threadIdx.x] = Wt3[threadIdx.x]; }
    if (threadIdx.x < 16) {
        sbp1[threadIdx.x] = bp1[threadIdx.x]; sbp2[threadIdx.x] = bp2[threadIdx.x];
        sbt1[threadIdx.x] = bt1[threadIdx.x]; sbt2[threadIdx.x] = bt2[threadIdx.x];
    }
    if (threadIdx.x < 2) { sbp3[threadIdx.x] = bp3[threadIdx.x]; sbt3[threadIdx.x] = bt3[threadIdx.x]; }
    __syncthreads();

    int g = blockIdx.x * blockDim.x + threadIdx.x;
    if (g >= GG) return;
    float p[16];
#pragma unroll
    for (int c = 0; c < 4; c++) {
        float4 v = g_pooled[g * 4 + c];
        p[4 * c + 0] = v.x; p[4 * c + 1] = v.y; p[4 * c + 2] = v.z; p[4 * c + 3] = v.w;
    }
    float a[16], b[16];
#pragma unroll
    for (int j = 0; j < 16; j++) {
        float s = sbp1[j];
#pragma unroll
        for (int k = 0; k < 16; k++) s += p[k] * sWp1[k * 16 + j];
        a[j] = lrelu(s);
    }
#pragma unroll
    for (int j = 0; j < 16; j++) {
        float s = sbp2[j];
#pragma unroll
        for (int k = 0; k < 16; k++) s += a[k] * sWp2[k * 16 + j];
        b[j] = lrelu(s);
    }
    float phi0 = sbp3[0], phi1 = sbp3[1];
#pragma unroll
    for (int k = 0; k < 16; k++) { phi0 += b[k] * sWp3[k * 2 + 0]; phi1 += b[k] * sWp3[k * 2 + 1]; }
#pragma unroll
    for (int j = 0; j < 16; j++) {
        float s = sbt1[j];
#pragma unroll
        for (int k = 0; k < 16; k++) s += p[k] * sWt1[k * 16 + j];
        a[j] = lrelu(s);
    }
#pragma unroll
    for (int j = 0; j < 16; j++) {
        float s = sbt2[j];
#pragma unroll
        for (int k = 0; k < 16; k++) s += a[k] * sWt2[k * 16 + j];
        b[j] = lrelu(s);
    }
    float th0 = sbt3[0], th1 = sbt3[1];
#pragma unroll
    for (int k = 0; k < 16; k++) { th0 += b[k] * sWt3[k * 2 + 0]; th1 += b[k] * sWt3[k * 2 + 1]; }

    out[g * 4 + 0] = phi0;
    out[g * 4 + 1] = phi1;
    out[g * 4 + 2] = th0;
    out[g * 4 + 3] = th1;
}

// ---------------------------------------------------------------------------
extern "C" void kernel_launch(void* const* d_in, const int* in_sizes, int n_in,
                              void* d_out, int out_size) {
    const float* X   = (const float*)d_in[0];
    const int*   ei  = (const int*)d_in[1];
    const float* ew  = (const float*)d_in[2];
    const int*   Bt  = (const int*)d_in[3];
    int base = 4;
    if (base < n_in && in_sizes[base] == 1) base++;  // skip scalar num_graphs
    const float* W1  = (const float*)d_in[base + 0];
    const float* b1  = (const float*)d_in[base + 1];
    const float* W2  = (const float*)d_in[base + 2];
    const float* b2  = (const float*)d_in[base + 3];
    const float* Wp1 = (const float*)d_in[base + 4];
    const float* bp1 = (const float*)d_in[base + 5];
    const float* Wp2 = (const float*)d_in[base + 6];
    const float* bp2 = (const float*)d_in[base + 7];
    const float* Wp3 = (const float*)d_in[base + 8];
    const float* bp3 = (const float*)d_in[base + 9];
    const float* Wt1 = (const float*)d_in[base + 10];
    const float* bt1 = (const float*)d_in[base + 11];
    const float* Wt2 = (const float*)d_in[base + 12];
    const float* bt2 = (const float*)d_in[base + 13];
    const float* Wt3 = (const float*)d_in[base + 14];
    const float* bt3 = (const float*)d_in[base + 15];

    const int* src = ei;
    const int* dst = ei + EE;
    float* out = (float*)d_out;

    k_init<<<NN / 256, 256>>>();
    k_deg<<<EE / 4 / 256, 256>>>(dst, ew);
    k_prep<<<NN / 256, 256>>>(X);
    k_edge1<<<EE / 256, 256>>>(src, dst, ew);
    k_mid<<<NN / 256, 256>>>(W1, b1);
    k_edge2<<<(2u * EE) / 256, 256>>>(src, dst, ew);
    k_post<<<NN / 256, 256>>>(W1, b1, W2, b2);
    k_pool<<<GG, 128>>>(Bt);
    k_mlp<<<(GG + 255) / 256, 256>>>(Wp1, bp1, Wp2, bp2, Wp3, bp3,
                                     Wt1, bt1, Wt2, bt2, Wt3, bt3, out);
}